// round 9
// baseline (speedup 1.0000x reference)
#include <cuda_runtime.h>
#include <cstdint>

#define T_TOK   8192
#define DMODEL  1024
#define DFF     4096
#define NEXP    8
#define TM      256                      // CTA M tile
#define TN      128                      // CTA N tile
#define MAX_TILES 72                     // 256-row tiles: 16384 + 8*255 pad <= 72*256
#define MAX_SLOTS (MAX_TILES * TM)       // 18432
#define KC 32
#define SA 36                            // As row stride (floats): conflict-free
#define SB 136                           // Bs row stride (floats)
#define NSTAGE 3
#define STAGE_A_F (TM * SA)              // 9216 floats
#define STAGE_B_F (KC * SB)              // 4352 floats
#define STAGE_F   (STAGE_A_F + STAGE_B_F) // 13568 floats
#define SMEM_BYTES (NSTAGE * STAGE_F * 4) // 162816 B

// ---------------- device scratch (no allocation allowed) ----------------
__device__ float g_h  [(size_t)MAX_SLOTS * DFF];        // hidden acts, tf32-rounded (302 MB)
__device__ float g_xr [(size_t)T_TOK * DMODEL];         // tf32-rounded x (32 MB)
__device__ float g_w1r[(size_t)NEXP * DMODEL * DFF];    // tf32-rounded w1 (128 MB)
__device__ float g_w2r[(size_t)NEXP * DFF * DMODEL];    // tf32-rounded w2 (128 MB)
__device__ int   g_slot_token[MAX_SLOTS];
__device__ float g_slot_gate[MAX_SLOTS];
__device__ int   g_counts[NEXP];
__device__ int   g_fill[NEXP];
__device__ int   g_offsets[NEXP];
__device__ int   g_tile_expert[MAX_TILES];
__device__ int   g_tok_expert[T_TOK * 2];
__device__ float g_tok_gate[T_TOK * 2];

// ---------------- helpers ----------------
__device__ __forceinline__ float tf32_rna(float x) {
    uint32_t u;
    asm("cvt.rna.tf32.f32 %0, %1;" : "=r"(u) : "f"(x));
    return __uint_as_float(u);
}
__device__ __forceinline__ void mma_tf32(float c[4], const uint32_t a[4], const uint32_t b[2]) {
    asm volatile(
        "mma.sync.aligned.m16n8k8.row.col.f32.tf32.tf32.f32 "
        "{%0,%1,%2,%3}, {%4,%5,%6,%7}, {%8,%9}, {%0,%1,%2,%3};\n"
        : "+f"(c[0]), "+f"(c[1]), "+f"(c[2]), "+f"(c[3])
        : "r"(a[0]), "r"(a[1]), "r"(a[2]), "r"(a[3]), "r"(b[0]), "r"(b[1]));
}
__device__ __forceinline__ void cp16(uint32_t smem_addr, const void* gmem, int src_bytes) {
    asm volatile("cp.async.cg.shared.global [%0], [%1], 16, %2;\n"
                 :: "r"(smem_addr), "l"(gmem), "r"(src_bytes));
}
__device__ __forceinline__ void cp_commit() {
    asm volatile("cp.async.commit_group;\n" ::: "memory");
}
__device__ __forceinline__ void cp_wait1() {
    asm volatile("cp.async.wait_group 1;\n" ::: "memory");
}

// ---------------- 0: reset ----------------
__global__ void reset_kernel() {
    int i = blockIdx.x * 256 + threadIdx.x;
    if (i < MAX_SLOTS) g_slot_token[i] = -1;
    if (i < NEXP) { g_counts[i] = 0; g_fill[i] = 0; }
}

// ---------------- 0b: tf32 pre-round (elementwise copy) ----------------
__global__ __launch_bounds__(256) void round_copy_kernel(
    const float4* __restrict__ src, float4* __restrict__ dst)
{
    size_t i = (size_t)blockIdx.x * 256 + threadIdx.x;
    float4 v = src[i];
    v.x = tf32_rna(v.x); v.y = tf32_rna(v.y);
    v.z = tf32_rna(v.z); v.w = tf32_rna(v.w);
    dst[i] = v;
}

// ---------------- 1: router (one warp per token) ----------------
__global__ __launch_bounds__(256) void router_kernel(
    const float* __restrict__ x, const float* __restrict__ noise_u,
    const float* __restrict__ wg, const float* __restrict__ bg,
    const float* __restrict__ wn, const float* __restrict__ bn)
{
    __shared__ float sW[512][20];
    const int tid = threadIdx.x;
    const int wid = tid >> 5, lane = tid & 31;
    const int t = blockIdx.x * 8 + wid;

    float acc[16];
    #pragma unroll
    for (int j = 0; j < 16; j++) acc[j] = 0.f;

    for (int c = 0; c < 2; c++) {
        #pragma unroll
        for (int it = 0; it < 8; it++) {
            int idx = it * 256 + tid;
            int row = idx >> 2, qq = idx & 3;
            int grow = c * 512 + row;
            float4 v;
            if (qq < 2) v = *(const float4*)(wg + (size_t)grow * NEXP + qq * 4);
            else        v = *(const float4*)(wn + (size_t)grow * NEXP + (qq - 2) * 4);
            *(float4*)&sW[row][qq * 4] = v;
        }
        __syncthreads();

        const float* xr = x + (size_t)t * DMODEL + c * 512;
        for (int kk = lane; kk < 512; kk += 32) {
            float xv = xr[kk];
            float4 a0 = *(const float4*)&sW[kk][0];
            float4 a1 = *(const float4*)&sW[kk][4];
            float4 b0 = *(const float4*)&sW[kk][8];
            float4 b1 = *(const float4*)&sW[kk][12];
            acc[0]  += xv * a0.x; acc[1]  += xv * a0.y; acc[2]  += xv * a0.z; acc[3]  += xv * a0.w;
            acc[4]  += xv * a1.x; acc[5]  += xv * a1.y; acc[6]  += xv * a1.z; acc[7]  += xv * a1.w;
            acc[8]  += xv * b0.x; acc[9]  += xv * b0.y; acc[10] += xv * b0.z; acc[11] += xv * b0.w;
            acc[12] += xv * b1.x; acc[13] += xv * b1.y; acc[14] += xv * b1.z; acc[15] += xv * b1.w;
        }
        __syncthreads();
    }

    #pragma unroll
    for (int j = 0; j < 16; j++) {
        float v = acc[j];
        #pragma unroll
        for (int o = 16; o > 0; o >>= 1) v += __shfl_xor_sync(0xffffffffu, v, o);
        acc[j] = v;
    }

    if (lane == 0) {
        float v0 = -1e30f, v1 = -1e30f;
        int i0 = 0, i1 = 0;
        #pragma unroll
        for (int e = 0; e < NEXP; e++) {
            float lg = acc[e] + bg[e];
            float nl = acc[8 + e] + bn[e];
            float sp = fmaxf(nl, 0.f) + log1pf(expf(-fabsf(nl)));
            float nz = lg + noise_u[(size_t)t * NEXP + e] * sp;
            if (nz > v0)      { v1 = v0; i1 = i0; v0 = nz; i0 = e; }
            else if (nz > v1) { v1 = nz; i1 = e; }
        }
        float e1 = expf(v1 - v0);
        float s  = 1.f + e1;
        int o = t * 2;
        g_tok_expert[o]     = i0; g_tok_gate[o]     = 1.f / s;
        g_tok_expert[o + 1] = i1; g_tok_gate[o + 1] = e1 / s;
        atomicAdd(&g_counts[i0], 1);
        atomicAdd(&g_counts[i1], 1);
    }
}

// ---------------- 2: offsets ----------------
__global__ void offsets_kernel() {
    if (threadIdx.x == 0 && blockIdx.x == 0) {
        int off = 0;
        for (int e = 0; e < NEXP; e++) {
            g_offsets[e] = off;
            int tiles = (g_counts[e] + TM - 1) / TM;
            for (int i = 0; i < tiles; i++) g_tile_expert[off / TM + i] = e;
            off += tiles * TM;
        }
        for (int i = off / TM; i < MAX_TILES; i++) g_tile_expert[i] = -1;
    }
}

// ---------------- 3: scatter ----------------
__global__ void scatter_kernel() {
    int i = blockIdx.x * 256 + threadIdx.x;
    if (i >= T_TOK * 2) return;
    int e = g_tok_expert[i];
    float gt = g_tok_gate[i];
    int pos = atomicAdd(&g_fill[e], 1);
    int slot = g_offsets[e] + pos;
    g_slot_token[slot] = i >> 1;
    g_slot_gate[slot]  = gt;
}

// ---------------- 4: zero output ----------------
__global__ void zero_out_kernel(float4* __restrict__ out) {
    out[(size_t)blockIdx.x * 256 + threadIdx.x] = make_float4(0.f, 0.f, 0.f, 0.f);
}

// ================= pipelined GEMM core: 8 warps, 64x64 warp tiles =================
// Warp grid: wm = wid>>1 (4 over M=256), wn = wid&1 (2 over N=128).
// Per warp: 4 m-subtiles x 8 n-subtiles of m16n8k8.
__device__ __forceinline__ void compute_chunk(
    const float* __restrict__ As, const float* __restrict__ Bs,
    int wm, int wn, int g, int tg, float acc[4][8][4])
{
    #pragma unroll
    for (int ks = 0; ks < KC / 8; ks++) {
        const int kb = ks * 8;
        uint32_t a[4][4], b[8][2];
        #pragma unroll
        for (int mt = 0; mt < 4; mt++) {
            const float* ap = As + (wm * 64 + mt * 16 + g) * SA + kb + tg;
            a[mt][0] = __float_as_uint(ap[0]);
            a[mt][1] = __float_as_uint(ap[8 * SA]);
            a[mt][2] = __float_as_uint(ap[4]);
            a[mt][3] = __float_as_uint(ap[8 * SA + 4]);
        }
        #pragma unroll
        for (int nt = 0; nt < 8; nt++) {
            const float* bp = Bs + (kb + tg) * SB + wn * 64 + nt * 8 + g;
            b[nt][0] = __float_as_uint(bp[0]);
            b[nt][1] = __float_as_uint(bp[4 * SB]);
        }
        #pragma unroll
        for (int mt = 0; mt < 4; mt++)
            #pragma unroll
            for (int nt = 0; nt < 8; nt++)
                mma_tf32(acc[mt][nt], a[mt], b[nt]);
    }
}

// ---------------- 5: gemm1  h = round(relu(gather(Xr) @ w1r[e] + b1)) ----------------
__global__ __launch_bounds__(256, 1) void gemm1_kernel(const float* __restrict__ b1)
{
    const int tile = blockIdx.y;
    const int e = g_tile_expert[tile];
    if (e < 0) return;
    const int n0 = blockIdx.x * TN;
    const int base = tile * TM;

    extern __shared__ float smem[];
    __shared__ int sTok[TM];

    const int tid = threadIdx.x;
    sTok[tid] = g_slot_token[base + tid];
    __syncthreads();

    const uint32_t smem_u32 = (uint32_t)__cvta_generic_to_shared(smem);
    const float* w1e = g_w1r + (size_t)e * DMODEL * DFF;

    // A: 256 rows x 32 k per stage; thread covers 8 rows (one per it), 16B at qA.
    const int qA = tid & 7;
    const float* srcA[8]; int szA[8];
    uint32_t dstA0 = smem_u32 + ((tid >> 3) * SA + qA * 4) * 4;
    #pragma unroll
    for (int it = 0; it < 8; it++) {
        int row = it * 32 + (tid >> 3);
        int t = sTok[row];
        srcA[it] = g_xr + (size_t)(t < 0 ? 0 : t) * DMODEL + qA * 4;
        szA[it]  = (t >= 0) ? 16 : 0;
    }
    // B: 32 k x 128 n per stage; thread covers 4 k-rows.
    const float* srcB0 = w1e + (size_t)(tid >> 5) * DFF + n0 + (tid & 31) * 4;
    uint32_t dstB0 = smem_u32 + (STAGE_A_F + (tid >> 5) * SB + (tid & 31) * 4) * 4;

    const int NCHUNK = DMODEL / KC;   // 32
    const int wid = tid >> 5, lane = tid & 31;
    const int wm = wid >> 1, wn = wid & 1;
    const int g = lane >> 2, tg = lane & 3;

    float acc[4][8][4];
    #pragma unroll
    for (int i = 0; i < 4; i++)
        #pragma unroll
        for (int j = 0; j < 8; j++)
            #pragma unroll
            for (int k = 0; k < 4; k++) acc[i][j][k] = 0.f;

    #pragma unroll
    for (int p = 0; p < NSTAGE - 1; p++) {
        uint32_t sb = p * (STAGE_F * 4);
        int k0 = p * KC;
        #pragma unroll
        for (int it = 0; it < 8; it++)
            cp16(dstA0 + sb + it * (32 * SA * 4), srcA[it] + k0, szA[it]);
        #pragma unroll
        for (int it = 0; it < 4; it++)
            cp16(dstB0 + sb + it * (8 * SB * 4), srcB0 + (size_t)k0 * DFF + (size_t)it * 8 * DFF, 16);
        cp_commit();
    }

    for (int i = 0; i < NCHUNK; i++) {
        cp_wait1();
        __syncthreads();
        int pc = i + NSTAGE - 1;
        if (pc < NCHUNK) {
            uint32_t sb = (pc % NSTAGE) * (STAGE_F * 4);
            int k0 = pc * KC;
            #pragma unroll
            for (int it = 0; it < 8; it++)
                cp16(dstA0 + sb + it * (32 * SA * 4), srcA[it] + k0, szA[it]);
            #pragma unroll
            for (int it = 0; it < 4; it++)
                cp16(dstB0 + sb + it * (8 * SB * 4), srcB0 + (size_t)k0 * DFF + (size_t)it * 8 * DFF, 16);
        }
        cp_commit();

        const float* As = smem + (i % NSTAGE) * STAGE_F;
        const float* Bs = As + STAGE_A_F;
        compute_chunk(As, Bs, wm, wn, g, tg, acc);
    }

    const float* b1e = b1 + (size_t)e * DFF + n0;
    #pragma unroll
    for (int mt = 0; mt < 4; mt++) {
        int row = wm * 64 + mt * 16 + g;
        #pragma unroll
        for (int nt = 0; nt < 8; nt++) {
            int col = wn * 64 + nt * 8 + tg * 2;
            float bb0 = b1e[col], bb1 = b1e[col + 1];
            float2 v0, v1;
            v0.x = tf32_rna(fmaxf(acc[mt][nt][0] + bb0, 0.f));
            v0.y = tf32_rna(fmaxf(acc[mt][nt][1] + bb1, 0.f));
            v1.x = tf32_rna(fmaxf(acc[mt][nt][2] + bb0, 0.f));
            v1.y = tf32_rna(fmaxf(acc[mt][nt][3] + bb1, 0.f));
            *(float2*)(g_h + (size_t)(base + row) * DFF + n0 + col) = v0;
            *(float2*)(g_h + (size_t)(base + row + 8) * DFF + n0 + col) = v1;
        }
    }
}

// ---------------- 6: gemm2  out[token] += gate * (h @ w2r[e] + b2) ----------------
__global__ __launch_bounds__(256, 1) void gemm2_kernel(
    const float* __restrict__ b2, float* __restrict__ out)
{
    const int tile = blockIdx.y;
    const int e = g_tile_expert[tile];
    if (e < 0) return;
    const int n0 = blockIdx.x * TN;
    const int base = tile * TM;

    extern __shared__ float smem[];
    __shared__ int   sTok[TM];
    __shared__ float sGate[TM];

    const int tid = threadIdx.x;
    sTok[tid]  = g_slot_token[base + tid];
    sGate[tid] = g_slot_gate[base + tid];
    __syncthreads();

    const uint32_t smem_u32 = (uint32_t)__cvta_generic_to_shared(smem);
    const float* w2e = g_w2r + (size_t)e * DFF * DMODEL;

    const int qA = tid & 7;
    const float* srcA0 = g_h + (size_t)(base + (tid >> 3)) * DFF + qA * 4;
    uint32_t dstA0 = smem_u32 + ((tid >> 3) * SA + qA * 4) * 4;
    const float* srcB0 = w2e + (size_t)(tid >> 5) * DMODEL + n0 + (tid & 31) * 4;
    uint32_t dstB0 = smem_u32 + (STAGE_A_F + (tid >> 5) * SB + (tid & 31) * 4) * 4;

    const int NCHUNK = DFF / KC;   // 128
    const int wid = tid >> 5, lane = tid & 31;
    const int wm = wid >> 1, wn = wid & 1;
    const int g = lane >> 2, tg = lane & 3;

    float acc[4][8][4];
    #pragma unroll
    for (int i = 0; i < 4; i++)
        #pragma unroll
        for (int j = 0; j < 8; j++)
            #pragma unroll
            for (int k = 0; k < 4; k++) acc[i][j][k] = 0.f;

    #pragma unroll
    for (int p = 0; p < NSTAGE - 1; p++) {
        uint32_t sb = p * (STAGE_F * 4);
        int k0 = p * KC;
        #pragma unroll
        for (int it = 0; it < 8; it++)
            cp16(dstA0 + sb + it * (32 * SA * 4), srcA0 + (size_t)it * 32 * DFF + k0, 16);
        #pragma unroll
        for (int it = 0; it < 4; it++)
            cp16(dstB0 + sb + it * (8 * SB * 4), srcB0 + (size_t)k0 * DMODEL + (size_t)it * 8 * DMODEL, 16);
        cp_commit();
    }

    for (int i = 0; i < NCHUNK; i++) {
        cp_wait1();
        __syncthreads();
        int pc = i + NSTAGE - 1;
        if (pc < NCHUNK) {
            uint32_t sb = (pc % NSTAGE) * (STAGE_F * 4);
            int k0 = pc * KC;
            #pragma unroll
            for (int it = 0; it < 8; it++)
                cp16(dstA0 + sb + it * (32 * SA * 4), srcA0 + (size_t)it * 32 * DFF + k0, 16);
            #pragma unroll
            for (int it = 0; it < 4; it++)
                cp16(dstB0 + sb + it * (8 * SB * 4), srcB0 + (size_t)k0 * DMODEL + (size_t)it * 8 * DMODEL, 16);
        }
        cp_commit();

        const float* As = smem + (i % NSTAGE) * STAGE_F;
        const float* Bs = As + STAGE_A_F;
        compute_chunk(As, Bs, wm, wn, g, tg, acc);
    }

    const float* b2e = b2 + (size_t)e * DMODEL + n0;
    #pragma unroll
    for (int mt = 0; mt < 4; mt++) {
        int row = wm * 64 + mt * 16 + g;
        int tk0 = sTok[row], tk1 = sTok[row + 8];
        float gt0 = sGate[row], gt1 = sGate[row + 8];
        #pragma unroll
        for (int nt = 0; nt < 8; nt++) {
            int col = wn * 64 + nt * 8 + tg * 2;
            float bb0 = b2e[col], bb1 = b2e[col + 1];
            if (tk0 >= 0) {
                atomicAdd(out + (size_t)tk0 * DMODEL + n0 + col,     gt0 * (acc[mt][nt][0] + bb0));
                atomicAdd(out + (size_t)tk0 * DMODEL + n0 + col + 1, gt0 * (acc[mt][nt][1] + bb1));
            }
            if (tk1 >= 0) {
                atomicAdd(out + (size_t)tk1 * DMODEL + n0 + col,     gt1 * (acc[mt][nt][2] + bb0));
                atomicAdd(out + (size_t)tk1 * DMODEL + n0 + col + 1, gt1 * (acc[mt][nt][3] + bb1));
            }
        }
    }
}

// ---------------- launch ----------------
extern "C" void kernel_launch(void* const* d_in, const int* in_sizes, int n_in,
                              void* d_out, int out_size)
{
    (void)in_sizes; (void)n_in; (void)out_size;
    const float* x       = (const float*)d_in[0];
    const float* noise_u = (const float*)d_in[1];
    const float* wg      = (const float*)d_in[2];
    const float* bg      = (const float*)d_in[3];
    const float* wn      = (const float*)d_in[4];
    const float* bn      = (const float*)d_in[5];
    const float* w1      = (const float*)d_in[6];
    const float* b1      = (const float*)d_in[7];
    const float* w2      = (const float*)d_in[8];
    const float* b2      = (const float*)d_in[9];
    float* out = (float*)d_out;

    float* xr;  cudaGetSymbolAddress((void**)&xr,  g_xr);
    float* w1r; cudaGetSymbolAddress((void**)&w1r, g_w1r);
    float* w2r; cudaGetSymbolAddress((void**)&w2r, g_w2r);

    cudaFuncSetAttribute(gemm1_kernel, cudaFuncAttributeMaxDynamicSharedMemorySize, SMEM_BYTES);
    cudaFuncSetAttribute(gemm2_kernel, cudaFuncAttributeMaxDynamicSharedMemorySize, SMEM_BYTES);

    reset_kernel<<<(MAX_SLOTS + 255) / 256, 256>>>();
    router_kernel<<<T_TOK / 8, 256>>>(x, noise_u, wg, bg, wn, bn);
    offsets_kernel<<<1, 32>>>();
    scatter_kernel<<<(T_TOK * 2) / 256, 256>>>();
    zero_out_kernel<<<(T_TOK * DMODEL) / (4 * 256), 256>>>((float4*)out);

    // tf32 pre-round passes (elementwise, HBM-bound)
    round_copy_kernel<<<(int)(((size_t)T_TOK * DMODEL / 4) / 256), 256>>>(
        (const float4*)x, (float4*)xr);
    round_copy_kernel<<<(int)(((size_t)NEXP * DMODEL * DFF / 4) / 256), 256>>>(
        (const float4*)w1, (float4*)w1r);
    round_copy_kernel<<<(int)(((size_t)NEXP * DFF * DMODEL / 4) / 256), 256>>>(
        (const float4*)w2, (float4*)w2r);

    gemm1_kernel<<<dim3(DFF / TN, MAX_TILES), 256, SMEM_BYTES>>>(b1);
    gemm2_kernel<<<dim3(DMODEL / TN, MAX_TILES), 256, SMEM_BYTES>>>(b2, out);
}

// round 10
// speedup vs baseline: 1.1290x; 1.1290x over previous
#include <cuda_runtime.h>
#include <cstdint>

#define T_TOK   8192
#define DMODEL  1024
#define DFF     4096
#define NEXP    8
#define MAX_SLOTS 17408          // 16384 assignments + per-expert pad to 128
#define MAX_TILES 136            // MAX_SLOTS / 128
#define KC 32
#define SA 36                    // As row stride (floats): conflict-free
#define SB 136                   // Bs row stride (floats)
#define NSTAGE 3
#define NTHR 128                 // 4 warps per CTA, 2 CTAs/SM
#define STAGE_A_F (128 * SA)             // 4608 floats
#define STAGE_B_F (KC * SB)              // 4352 floats
#define STAGE_F   (STAGE_A_F + STAGE_B_F) // 8960 floats
#define SMEM_BYTES (NSTAGE * STAGE_F * 4) // 107520 B

// ---------------- device scratch (no allocation allowed) ----------------
__device__ float g_h  [(size_t)MAX_SLOTS * DFF];        // hidden acts, tf32-rounded (285 MB)
__device__ float g_xr [(size_t)T_TOK * DMODEL];         // tf32-rounded x (32 MB)
__device__ float g_w1r[(size_t)NEXP * DMODEL * DFF];    // tf32-rounded w1 (128 MB)
__device__ float g_w2r[(size_t)NEXP * DFF * DMODEL];    // tf32-rounded w2 (128 MB)
__device__ int   g_slot_token[MAX_SLOTS];
__device__ float g_slot_gate[MAX_SLOTS];
__device__ int   g_counts[NEXP];
__device__ int   g_fill[NEXP];
__device__ int   g_offsets[NEXP];
__device__ int   g_tile_expert[MAX_TILES];
__device__ int   g_tok_expert[T_TOK * 2];
__device__ float g_tok_gate[T_TOK * 2];

// ---------------- helpers ----------------
__device__ __forceinline__ float tf32_rna(float x) {
    uint32_t u;
    asm("cvt.rna.tf32.f32 %0, %1;" : "=r"(u) : "f"(x));
    return __uint_as_float(u);
}
__device__ __forceinline__ void mma_tf32(float c[4], const uint32_t a[4], const uint32_t b[2]) {
    asm volatile(
        "mma.sync.aligned.m16n8k8.row.col.f32.tf32.tf32.f32 "
        "{%0,%1,%2,%3}, {%4,%5,%6,%7}, {%8,%9}, {%0,%1,%2,%3};\n"
        : "+f"(c[0]), "+f"(c[1]), "+f"(c[2]), "+f"(c[3])
        : "r"(a[0]), "r"(a[1]), "r"(a[2]), "r"(a[3]), "r"(b[0]), "r"(b[1]));
}
__device__ __forceinline__ void cp16(uint32_t smem_addr, const void* gmem, int src_bytes) {
    asm volatile("cp.async.cg.shared.global [%0], [%1], 16, %2;\n"
                 :: "r"(smem_addr), "l"(gmem), "r"(src_bytes));
}
__device__ __forceinline__ void cp_commit() {
    asm volatile("cp.async.commit_group;\n" ::: "memory");
}
__device__ __forceinline__ void cp_wait1() {
    asm volatile("cp.async.wait_group 1;\n" ::: "memory");
}

// ---------------- 0: reset ----------------
__global__ void reset_kernel() {
    int i = blockIdx.x * 256 + threadIdx.x;
    if (i < MAX_SLOTS) g_slot_token[i] = -1;
    if (i < NEXP) { g_counts[i] = 0; g_fill[i] = 0; }
}

// ---------------- 0b: tf32 pre-round (elementwise copy) ----------------
__global__ __launch_bounds__(256) void round_copy_kernel(
    const float4* __restrict__ src, float4* __restrict__ dst)
{
    size_t i = (size_t)blockIdx.x * 256 + threadIdx.x;
    float4 v = src[i];
    v.x = tf32_rna(v.x); v.y = tf32_rna(v.y);
    v.z = tf32_rna(v.z); v.w = tf32_rna(v.w);
    dst[i] = v;
}

// ---------------- 1: router (one warp per token) ----------------
__global__ __launch_bounds__(256) void router_kernel(
    const float* __restrict__ x, const float* __restrict__ noise_u,
    const float* __restrict__ wg, const float* __restrict__ bg,
    const float* __restrict__ wn, const float* __restrict__ bn)
{
    __shared__ float sW[512][20];
    const int tid = threadIdx.x;
    const int wid = tid >> 5, lane = tid & 31;
    const int t = blockIdx.x * 8 + wid;

    float acc[16];
    #pragma unroll
    for (int j = 0; j < 16; j++) acc[j] = 0.f;

    for (int c = 0; c < 2; c++) {
        #pragma unroll
        for (int it = 0; it < 8; it++) {
            int idx = it * 256 + tid;
            int row = idx >> 2, qq = idx & 3;
            int grow = c * 512 + row;
            float4 v;
            if (qq < 2) v = *(const float4*)(wg + (size_t)grow * NEXP + qq * 4);
            else        v = *(const float4*)(wn + (size_t)grow * NEXP + (qq - 2) * 4);
            *(float4*)&sW[row][qq * 4] = v;
        }
        __syncthreads();

        const float* xr = x + (size_t)t * DMODEL + c * 512;
        for (int kk = lane; kk < 512; kk += 32) {
            float xv = xr[kk];
            float4 a0 = *(const float4*)&sW[kk][0];
            float4 a1 = *(const float4*)&sW[kk][4];
            float4 b0 = *(const float4*)&sW[kk][8];
            float4 b1 = *(const float4*)&sW[kk][12];
            acc[0]  += xv * a0.x; acc[1]  += xv * a0.y; acc[2]  += xv * a0.z; acc[3]  += xv * a0.w;
            acc[4]  += xv * a1.x; acc[5]  += xv * a1.y; acc[6]  += xv * a1.z; acc[7]  += xv * a1.w;
            acc[8]  += xv * b0.x; acc[9]  += xv * b0.y; acc[10] += xv * b0.z; acc[11] += xv * b0.w;
            acc[12] += xv * b1.x; acc[13] += xv * b1.y; acc[14] += xv * b1.z; acc[15] += xv * b1.w;
        }
        __syncthreads();
    }

    #pragma unroll
    for (int j = 0; j < 16; j++) {
        float v = acc[j];
        #pragma unroll
        for (int o = 16; o > 0; o >>= 1) v += __shfl_xor_sync(0xffffffffu, v, o);
        acc[j] = v;
    }

    if (lane == 0) {
        float v0 = -1e30f, v1 = -1e30f;
        int i0 = 0, i1 = 0;
        #pragma unroll
        for (int e = 0; e < NEXP; e++) {
            float lg = acc[e] + bg[e];
            float nl = acc[8 + e] + bn[e];
            float sp = fmaxf(nl, 0.f) + log1pf(expf(-fabsf(nl)));
            float nz = lg + noise_u[(size_t)t * NEXP + e] * sp;
            if (nz > v0)      { v1 = v0; i1 = i0; v0 = nz; i0 = e; }
            else if (nz > v1) { v1 = nz; i1 = e; }
        }
        float e1 = expf(v1 - v0);
        float s  = 1.f + e1;
        int o = t * 2;
        g_tok_expert[o]     = i0; g_tok_gate[o]     = 1.f / s;
        g_tok_expert[o + 1] = i1; g_tok_gate[o + 1] = e1 / s;
        atomicAdd(&g_counts[i0], 1);
        atomicAdd(&g_counts[i1], 1);
    }
}

// ---------------- 2: offsets ----------------
__global__ void offsets_kernel() {
    if (threadIdx.x == 0 && blockIdx.x == 0) {
        int off = 0;
        for (int e = 0; e < NEXP; e++) {
            g_offsets[e] = off;
            int tiles = (g_counts[e] + 127) >> 7;
            for (int i = 0; i < tiles; i++) g_tile_expert[(off >> 7) + i] = e;
            off += tiles << 7;
        }
        for (int i = off >> 7; i < MAX_TILES; i++) g_tile_expert[i] = -1;
    }
}

// ---------------- 3: scatter ----------------
__global__ void scatter_kernel() {
    int i = blockIdx.x * 256 + threadIdx.x;
    if (i >= T_TOK * 2) return;
    int e = g_tok_expert[i];
    float gt = g_tok_gate[i];
    int pos = atomicAdd(&g_fill[e], 1);
    int slot = g_offsets[e] + pos;
    g_slot_token[slot] = i >> 1;
    g_slot_gate[slot]  = gt;
}

// ---------------- 4: zero output ----------------
__global__ void zero_out_kernel(float4* __restrict__ out) {
    out[(size_t)blockIdx.x * 256 + threadIdx.x] = make_float4(0.f, 0.f, 0.f, 0.f);
}

// ================= GEMM core: 4 warps (2m x 2n), 64x64 warp tiles, 2 CTAs/SM =================
__device__ __forceinline__ void compute_chunk(
    const float* __restrict__ As, const float* __restrict__ Bs,
    int wm, int wn, int g, int tg, float acc[4][8][4])
{
    #pragma unroll
    for (int ks = 0; ks < KC / 8; ks++) {
        const int kb = ks * 8;
        uint32_t a[4][4], b[8][2];
        #pragma unroll
        for (int mt = 0; mt < 4; mt++) {
            const float* ap = As + (wm * 64 + mt * 16 + g) * SA + kb + tg;
            a[mt][0] = __float_as_uint(ap[0]);
            a[mt][1] = __float_as_uint(ap[8 * SA]);
            a[mt][2] = __float_as_uint(ap[4]);
            a[mt][3] = __float_as_uint(ap[8 * SA + 4]);
        }
        #pragma unroll
        for (int nt = 0; nt < 8; nt++) {
            const float* bp = Bs + (kb + tg) * SB + wn * 64 + nt * 8 + g;
            b[nt][0] = __float_as_uint(bp[0]);
            b[nt][1] = __float_as_uint(bp[4 * SB]);
        }
        #pragma unroll
        for (int mt = 0; mt < 4; mt++)
            #pragma unroll
            for (int nt = 0; nt < 8; nt++)
                mma_tf32(acc[mt][nt], a[mt], b[nt]);
    }
}

// ---------------- 5: gemm1  h = round(relu(gather(Xr) @ w1r[e] + b1)) ----------------
__global__ __launch_bounds__(NTHR, 2) void gemm1_kernel(const float* __restrict__ b1)
{
    const int tile = blockIdx.y;
    const int e = g_tile_expert[tile];
    if (e < 0) return;
    const int n0 = blockIdx.x * 128;
    const int base = tile * 128;

    extern __shared__ float smem[];
    __shared__ int sTok[128];

    const int tid = threadIdx.x;
    sTok[tid] = g_slot_token[base + tid];
    __syncthreads();

    const uint32_t smem_u32 = (uint32_t)__cvta_generic_to_shared(smem);
    const float* w1e = g_w1r + (size_t)e * DMODEL * DFF;

    // A: 128 rows x 32 k per stage; 128 thr -> 16 rows per it, 8 its.
    const int qA = tid & 7;
    const float* srcA[8]; int szA[8];
    uint32_t dstA0 = smem_u32 + ((tid >> 3) * SA + qA * 4) * 4;
    #pragma unroll
    for (int it = 0; it < 8; it++) {
        int row = it * 16 + (tid >> 3);
        int t = sTok[row];
        srcA[it] = g_xr + (size_t)(t < 0 ? 0 : t) * DMODEL + qA * 4;
        szA[it]  = (t >= 0) ? 16 : 0;
    }
    // B: 32 k x 128 n per stage; 128 thr -> 4 k-rows per it, 8 its.
    const float* srcB0 = w1e + (size_t)(tid >> 5) * DFF + n0 + (tid & 31) * 4;
    uint32_t dstB0 = smem_u32 + (STAGE_A_F + (tid >> 5) * SB + (tid & 31) * 4) * 4;

    const int NCHUNK = DMODEL / KC;   // 32
    const int wid = tid >> 5, lane = tid & 31;
    const int wm = wid >> 1, wn = wid & 1;
    const int g = lane >> 2, tg = lane & 3;

    float acc[4][8][4];
    #pragma unroll
    for (int i = 0; i < 4; i++)
        #pragma unroll
        for (int j = 0; j < 8; j++)
            #pragma unroll
            for (int k = 0; k < 4; k++) acc[i][j][k] = 0.f;

    #pragma unroll
    for (int p = 0; p < NSTAGE - 1; p++) {
        uint32_t sb = p * (STAGE_F * 4);
        int k0 = p * KC;
        #pragma unroll
        for (int it = 0; it < 8; it++)
            cp16(dstA0 + sb + it * (16 * SA * 4), srcA[it] + k0, szA[it]);
        #pragma unroll
        for (int it = 0; it < 8; it++)
            cp16(dstB0 + sb + it * (4 * SB * 4), srcB0 + (size_t)k0 * DFF + (size_t)it * 4 * DFF, 16);
        cp_commit();
    }

    for (int i = 0; i < NCHUNK; i++) {
        cp_wait1();
        __syncthreads();
        int pc = i + NSTAGE - 1;
        if (pc < NCHUNK) {
            uint32_t sb = (pc % NSTAGE) * (STAGE_F * 4);
            int k0 = pc * KC;
            #pragma unroll
            for (int it = 0; it < 8; it++)
                cp16(dstA0 + sb + it * (16 * SA * 4), srcA[it] + k0, szA[it]);
            #pragma unroll
            for (int it = 0; it < 8; it++)
                cp16(dstB0 + sb + it * (4 * SB * 4), srcB0 + (size_t)k0 * DFF + (size_t)it * 4 * DFF, 16);
        }
        cp_commit();

        const float* As = smem + (i % NSTAGE) * STAGE_F;
        const float* Bs = As + STAGE_A_F;
        compute_chunk(As, Bs, wm, wn, g, tg, acc);
    }

    const float* b1e = b1 + (size_t)e * DFF + n0;
    #pragma unroll
    for (int mt = 0; mt < 4; mt++) {
        int row = wm * 64 + mt * 16 + g;
        #pragma unroll
        for (int nt = 0; nt < 8; nt++) {
            int col = wn * 64 + nt * 8 + tg * 2;
            float bb0 = b1e[col], bb1 = b1e[col + 1];
            float2 v0, v1;
            v0.x = tf32_rna(fmaxf(acc[mt][nt][0] + bb0, 0.f));
            v0.y = tf32_rna(fmaxf(acc[mt][nt][1] + bb1, 0.f));
            v1.x = tf32_rna(fmaxf(acc[mt][nt][2] + bb0, 0.f));
            v1.y = tf32_rna(fmaxf(acc[mt][nt][3] + bb1, 0.f));
            *(float2*)(g_h + (size_t)(base + row) * DFF + n0 + col) = v0;
            *(float2*)(g_h + (size_t)(base + row + 8) * DFF + n0 + col) = v1;
        }
    }
}

// ---------------- 6: gemm2  out[token] += gate * (h @ w2r[e] + b2) ----------------
__global__ __launch_bounds__(NTHR, 2) void gemm2_kernel(
    const float* __restrict__ b2, float* __restrict__ out)
{
    const int tile = blockIdx.y;
    const int e = g_tile_expert[tile];
    if (e < 0) return;
    const int n0 = blockIdx.x * 128;
    const int base = tile * 128;

    extern __shared__ float smem[];
    __shared__ int   sTok[128];
    __shared__ float sGate[128];

    const int tid = threadIdx.x;
    sTok[tid]  = g_slot_token[base + tid];
    sGate[tid] = g_slot_gate[base + tid];
    __syncthreads();

    const uint32_t smem_u32 = (uint32_t)__cvta_generic_to_shared(smem);
    const float* w2e = g_w2r + (size_t)e * DFF * DMODEL;

    const int qA = tid & 7;
    const float* srcA0 = g_h + (size_t)(base + (tid >> 3)) * DFF + qA * 4;
    uint32_t dstA0 = smem_u32 + ((tid >> 3) * SA + qA * 4) * 4;
    const float* srcB0 = w2e + (size_t)(tid >> 5) * DMODEL + n0 + (tid & 31) * 4;
    uint32_t dstB0 = smem_u32 + (STAGE_A_F + (tid >> 5) * SB + (tid & 31) * 4) * 4;

    const int NCHUNK = DFF / KC;   // 128
    const int wid = tid >> 5, lane = tid & 31;
    const int wm = wid >> 1, wn = wid & 1;
    const int g = lane >> 2, tg = lane & 3;

    float acc[4][8][4];
    #pragma unroll
    for (int i = 0; i < 4; i++)
        #pragma unroll
        for (int j = 0; j < 8; j++)
            #pragma unroll
            for (int k = 0; k < 4; k++) acc[i][j][k] = 0.f;

    #pragma unroll
    for (int p = 0; p < NSTAGE - 1; p++) {
        uint32_t sb = p * (STAGE_F * 4);
        int k0 = p * KC;
        #pragma unroll
        for (int it = 0; it < 8; it++)
            cp16(dstA0 + sb + it * (16 * SA * 4), srcA0 + (size_t)it * 16 * DFF + k0, 16);
        #pragma unroll
        for (int it = 0; it < 8; it++)
            cp16(dstB0 + sb + it * (4 * SB * 4), srcB0 + (size_t)k0 * DMODEL + (size_t)it * 4 * DMODEL, 16);
        cp_commit();
    }

    for (int i = 0; i < NCHUNK; i++) {
        cp_wait1();
        __syncthreads();
        int pc = i + NSTAGE - 1;
        if (pc < NCHUNK) {
            uint32_t sb = (pc % NSTAGE) * (STAGE_F * 4);
            int k0 = pc * KC;
            #pragma unroll
            for (int it = 0; it < 8; it++)
                cp16(dstA0 + sb + it * (16 * SA * 4), srcA0 + (size_t)it * 16 * DFF + k0, 16);
            #pragma unroll
            for (int it = 0; it < 8; it++)
                cp16(dstB0 + sb + it * (4 * SB * 4), srcB0 + (size_t)k0 * DMODEL + (size_t)it * 4 * DMODEL, 16);
        }
        cp_commit();

        const float* As = smem + (i % NSTAGE) * STAGE_F;
        const float* Bs = As + STAGE_A_F;
        compute_chunk(As, Bs, wm, wn, g, tg, acc);
    }

    const float* b2e = b2 + (size_t)e * DMODEL + n0;
    #pragma unroll
    for (int mt = 0; mt < 4; mt++) {
        int row = wm * 64 + mt * 16 + g;
        int tk0 = sTok[row], tk1 = sTok[row + 8];
        float gt0 = sGate[row], gt1 = sGate[row + 8];
        #pragma unroll
        for (int nt = 0; nt < 8; nt++) {
            int col = wn * 64 + nt * 8 + tg * 2;
            float bb0 = b2e[col], bb1 = b2e[col + 1];
            if (tk0 >= 0) {
                atomicAdd(out + (size_t)tk0 * DMODEL + n0 + col,     gt0 * (acc[mt][nt][0] + bb0));
                atomicAdd(out + (size_t)tk0 * DMODEL + n0 + col + 1, gt0 * (acc[mt][nt][1] + bb1));
            }
            if (tk1 >= 0) {
                atomicAdd(out + (size_t)tk1 * DMODEL + n0 + col,     gt1 * (acc[mt][nt][2] + bb0));
                atomicAdd(out + (size_t)tk1 * DMODEL + n0 + col + 1, gt1 * (acc[mt][nt][3] + bb1));
            }
        }
    }
}

// ---------------- launch ----------------
extern "C" void kernel_launch(void* const* d_in, const int* in_sizes, int n_in,
                              void* d_out, int out_size)
{
    (void)in_sizes; (void)n_in; (void)out_size;
    const float* x       = (const float*)d_in[0];
    const float* noise_u = (const float*)d_in[1];
    const float* wg      = (const float*)d_in[2];
    const float* bg      = (const float*)d_in[3];
    const float* wn      = (const float*)d_in[4];
    const float* bn      = (const float*)d_in[5];
    const float* w1      = (const float*)d_in[6];
    const float* b1      = (const float*)d_in[7];
    const float* w2      = (const float*)d_in[8];
    const float* b2      = (const float*)d_in[9];
    float* out = (float*)d_out;

    float* xr;  cudaGetSymbolAddress((void**)&xr,  g_xr);
    float* w1r; cudaGetSymbolAddress((void**)&w1r, g_w1r);
    float* w2r; cudaGetSymbolAddress((void**)&w2r, g_w2r);

    cudaFuncSetAttribute(gemm1_kernel, cudaFuncAttributeMaxDynamicSharedMemorySize, SMEM_BYTES);
    cudaFuncSetAttribute(gemm2_kernel, cudaFuncAttributeMaxDynamicSharedMemorySize, SMEM_BYTES);

    reset_kernel<<<(MAX_SLOTS + 255) / 256, 256>>>();
    router_kernel<<<T_TOK / 8, 256>>>(x, noise_u, wg, bg, wn, bn);
    offsets_kernel<<<1, 32>>>();
    scatter_kernel<<<(T_TOK * 2) / 256, 256>>>();
    zero_out_kernel<<<(T_TOK * DMODEL) / (4 * 256), 256>>>((float4*)out);

    // tf32 pre-round passes (elementwise, HBM-bound)
    round_copy_kernel<<<(int)(((size_t)T_TOK * DMODEL / 4) / 256), 256>>>(
        (const float4*)x, (float4*)xr);
    round_copy_kernel<<<(int)(((size_t)NEXP * DMODEL * DFF / 4) / 256), 256>>>(
        (const float4*)w1, (float4*)w1r);
    round_copy_kernel<<<(int)(((size_t)NEXP * DFF * DMODEL / 4) / 256), 256>>>(
        (const float4*)w2, (float4*)w2r);

    gemm1_kernel<<<dim3(DFF / 128, MAX_TILES), NTHR, SMEM_BYTES>>>(b1);
    gemm2_kernel<<<dim3(DMODEL / 128, MAX_TILES), NTHR, SMEM_BYTES>>>(b2, out);
}